// round 11
// baseline (speedup 1.0000x reference)
#include <cuda_runtime.h>
#include <cuda_fp16.h>

// ZINB decoder over 3M edges.
// Stage 1: fused fp32 -> fp16 feature-table conversion (row = one 128B line).
// Stage 2: persistent kernel, warp = 16 consecutive edges/iter (4 sets x 4
//   groups, 8 lanes/edge). Feature tiles are prefetched ONE tile ahead into a
//   per-warp double-buffered SMEM region via cp.async (16B per lane), so the
//   L2 gather latency is off the critical path WITHOUT the register cost that
//   killed occupancy in the register-double-buffer attempt. Each lane reads
//   back exactly the smem bytes it wrote -> per-thread cp.async visibility,
//   zero barriers. Compute streams sets from smem with 1-set lookahead (16
//   live feature regs). f32x2 packed-FMA dots, reduce-scatter (12 SHFL),
//   16-lane fast-math epilogue, coalesced stores, 2-ahead index prefetch.

#define BLOCK 256
#define N_CELLS_MAX 50000
#define N_GENES_MAX 20000
#define TILE_BYTES 4096              // 32 rows x 128B per warp-tile
#define WARP_SMEM (2 * TILE_BYTES)   // double buffer per warp
#define SMEM_TOTAL (WARP_SMEM * (BLOCK / 32))

__device__ __align__(16) static __half c_half_tbl[N_CELLS_MAX * 64];
__device__ __align__(16) static __half g_half_tbl[N_GENES_MAX * 64];

typedef unsigned long long u64;

__device__ __forceinline__ u64 pack2(float x, float y) {
    u64 r; asm("mov.b64 %0, {%1,%2};" : "=l"(r) : "f"(x), "f"(y)); return r;
}
__device__ __forceinline__ u64 fma2(u64 a, u64 b, u64 c) {
    u64 d; asm("fma.rn.f32x2 %0, %1, %2, %3;" : "=l"(d) : "l"(a), "l"(b), "l"(c)); return d;
}
__device__ __forceinline__ float unpack_sum(u64 v) {
    float lo, hi; asm("mov.b64 {%0,%1}, %2;" : "=f"(lo), "=f"(hi) : "l"(v));
    return lo + hi;
}
__device__ __forceinline__ unsigned int h2_as_u32(__half2 h) {
    return *reinterpret_cast<unsigned int*>(&h);
}

// Fused fp32 -> fp16 conversion for both tables (8 floats per thread).
__global__ __launch_bounds__(256)
void cvt_fp16_kernel(const float* __restrict__ srcA, __half* __restrict__ dstA, int nA8,
                     const float* __restrict__ srcB, __half* __restrict__ dstB, int nB8) {
    int i = blockIdx.x * blockDim.x + threadIdx.x;
    const float* src; __half* dst; int j;
    if (i < nA8) { src = srcA; dst = dstA; j = i; }
    else if (i < nA8 + nB8) { src = srcB; dst = dstB; j = i - nA8; }
    else return;
    const float4* s = reinterpret_cast<const float4*>(src) + 2 * (size_t)j;
    const float4 a = s[0], b = s[1];
    uint4 o;
    o.x = h2_as_u32(__floats2half2_rn(a.x, a.y));
    o.y = h2_as_u32(__floats2half2_rn(a.z, a.w));
    o.z = h2_as_u32(__floats2half2_rn(b.x, b.y));
    o.w = h2_as_u32(__floats2half2_rn(b.z, b.w));
    reinterpret_cast<uint4*>(dst)[j] = o;
}

struct IdxTile { int u0, v0, u1, v1, u2, v2, u3, v3; };

__device__ __forceinline__ IdxTile load_idx(const int* __restrict__ eu,
                                            const int* __restrict__ ev,
                                            int ebase, int grp, int n_edges) {
    const int e0 = ebase + grp;
    const int ec0 = (e0      < n_edges) ? e0      : 0;
    const int ec1 = (e0 + 4  < n_edges) ? e0 + 4  : 0;
    const int ec2 = (e0 + 8  < n_edges) ? e0 + 8  : 0;
    const int ec3 = (e0 + 12 < n_edges) ? e0 + 12 : 0;
    IdxTile t;
    t.u0 = eu[ec0]; t.v0 = ev[ec0];
    t.u1 = eu[ec1]; t.v1 = ev[ec1];
    t.u2 = eu[ec2]; t.v2 = ev[ec2];
    t.u3 = eu[ec3]; t.v3 = ev[ec3];
    return t;
}

// Issue 8 cp.async (16B each): chunk lane8 of c/g rows for sets 0..3.
// smem row r(s,cg,grp) = (s*2+cg)*4 + grp; lane's dst = r*128 + lane8*16.
__device__ __forceinline__ void cp_tile(unsigned dstBase,
                                        const __half* __restrict__ c_feat,
                                        const __half* __restrict__ g_feat,
                                        const IdxTile& ix, int grp, int lane8) {
    const unsigned d = dstBase + (unsigned)(grp * 128 + lane8 * 16);
    const char* cb = reinterpret_cast<const char*>(c_feat);
    const char* gb = reinterpret_cast<const char*>(g_feat);
    const int co = lane8 * 16;
#define CP_ONE(S, CG, ROWPTR)                                                   \
    asm volatile("cp.async.ca.shared.global [%0], [%1], 16;"                    \
                 :: "r"(d + (unsigned)(((S)*2+(CG)) * 512)), "l"(ROWPTR) : "memory");
    CP_ONE(0, 0, cb + (size_t)ix.u0 * 128 + co)
    CP_ONE(0, 1, gb + (size_t)ix.v0 * 128 + co)
    CP_ONE(1, 0, cb + (size_t)ix.u1 * 128 + co)
    CP_ONE(1, 1, gb + (size_t)ix.v1 * 128 + co)
    CP_ONE(2, 0, cb + (size_t)ix.u2 * 128 + co)
    CP_ONE(2, 1, gb + (size_t)ix.v2 * 128 + co)
    CP_ONE(3, 0, cb + (size_t)ix.u3 * 128 + co)
    CP_ONE(3, 1, gb + (size_t)ix.v3 * 128 + co)
#undef CP_ONE
    asm volatile("cp.async.commit_group;" ::: "memory");
}

__global__ __launch_bounds__(BLOCK, 3)
void zinb_decoder_kernel(const __half* __restrict__ c_feat,
                         const __half* __restrict__ g_feat,
                         const float* __restrict__ cs_factor,
                         const float* __restrict__ gs_factor,
                         const int*   __restrict__ edge_u,
                         const int*   __restrict__ edge_v,
                         const float* __restrict__ W_mean,
                         const float* __restrict__ b_mean,
                         const float* __restrict__ W_disp,
                         const float* __restrict__ b_disp,
                         const float* __restrict__ W_pi,
                         const float* __restrict__ b_pi,
                         float* __restrict__ out,
                         int n_edges)
{
    extern __shared__ char smem[];
    const unsigned FULL = 0xffffffffu;
    const int warpLane = threadIdx.x & 31;
    const int grp      = warpLane >> 3;
    const int lane8    = warpLane & 7;
    const int sl       = ((warpLane & 4) >> 1) | ((warpLane & 2) >> 1);
    const int eoOff    = 4 * sl + grp;

    char* wsm = smem + (threadIdx.x >> 5) * WARP_SMEM;
    const unsigned wsmAddr = (unsigned)__cvta_generic_to_shared(wsm);

    // ---- weights packed as f32x2, biases ----
    const float4* wmv = reinterpret_cast<const float4*>(W_mean) + lane8 * 2;
    const float4* wdv = reinterpret_cast<const float4*>(W_disp) + lane8 * 2;
    const float4* wpv = reinterpret_cast<const float4*>(W_pi)   + lane8 * 2;
    const float4 a0 = __ldg(wmv), a1 = __ldg(wmv + 1);
    const float4 d0 = __ldg(wdv), d1 = __ldg(wdv + 1);
    const float4 p0 = __ldg(wpv), p1 = __ldg(wpv + 1);
    const u64 wm0 = pack2(a0.x, a0.y), wm1 = pack2(a0.z, a0.w),
              wm2 = pack2(a1.x, a1.y), wm3 = pack2(a1.z, a1.w);
    const u64 wd0 = pack2(d0.x, d0.y), wd1 = pack2(d0.z, d0.w),
              wd2 = pack2(d1.x, d1.y), wd3 = pack2(d1.z, d1.w);
    const u64 wp0 = pack2(p0.x, p0.y), wp1 = pack2(p0.z, p0.w),
              wp2 = pack2(p1.x, p1.y), wp3 = pack2(p1.z, p1.w);
    const float bm = __ldg(b_mean), bd = __ldg(b_disp), bp = __ldg(b_pi);

    const int warpId  = (blockIdx.x * BLOCK + threadIdx.x) >> 5;
    const int nWarps  = gridDim.x * (BLOCK >> 5);
    const int tileStr = nWarps * 16;

    const int e0 = warpId * 16;
    if (e0 >= n_edges) return;

    // ---- prime: indices for tiles 0,1; cp.async features for tile 0 ----
    IdxTile ia = load_idx(edge_u, edge_v, e0,           grp, n_edges);
    IdxTile ib = load_idx(edge_u, edge_v, e0 + tileStr, grp, n_edges);
    cp_tile(wsmAddr, c_feat, g_feat, ia, grp, lane8);

    int stage = 0;
    for (int ebase = e0; ebase < n_edges; ebase += tileStr) {
        // prefetch tile t+1 features into the other stage; indices for t+2
        cp_tile(wsmAddr + (stage ^ 1) * TILE_BYTES, c_feat, g_feat, ib, grp, lane8);
        IdxTile ic = load_idx(edge_u, edge_v, ebase + 2 * tileStr, grp, n_edges);

        // cs/gs scattered gathers (small cache-resident tables -> cheap hits)
        const int uSel = sl < 2 ? (sl == 0 ? ia.u0 : ia.u1) : (sl == 2 ? ia.u2 : ia.u3);
        const int vSel = sl < 2 ? (sl == 0 ? ia.v0 : ia.v1) : (sl == 2 ? ia.v2 : ia.v3);
        const float GS = gs_factor[vSel];
        const float CS = cs_factor[uSel];

        // wait for tile t's cp.async group (1 newer group may stay pending)
        asm volatile("cp.async.wait_group 1;" ::: "memory");

        // ---- stream sets from smem with 1-set lookahead ----
        const uint4* tile = reinterpret_cast<const uint4*>(wsm + stage * TILE_BYTES);
        const int base = grp * 8 + lane8;     // uint4 index of this lane's chunk
        uint4 C = tile[base];                 // set 0, cg=0  (rows at (s*2+cg)*32)
        uint4 G = tile[base + 32];            // set 0, cg=1

        float m[4], d[4], p[4];
        #pragma unroll
        for (int s = 0; s < 4; s++) {
            uint4 Cn, Gn;
            if (s < 3) {
                Cn = tile[base + (s + 1) * 64];
                Gn = tile[base + (s + 1) * 64 + 32];
            }
            const __half2* ch = reinterpret_cast<const __half2*>(&C);
            const __half2* gh = reinterpret_cast<const __half2*>(&G);
            const float2 q0 = __half22float2(__hmul2(ch[0], gh[0]));
            const float2 q1 = __half22float2(__hmul2(ch[1], gh[1]));
            const float2 q2 = __half22float2(__hmul2(ch[2], gh[2]));
            const float2 q3 = __half22float2(__hmul2(ch[3], gh[3]));
            const u64 h0 = pack2(q0.x, q0.y), h1 = pack2(q1.x, q1.y);
            const u64 h2 = pack2(q2.x, q2.y), h3 = pack2(q3.x, q3.y);
            u64 am = fma2(h0, wm0, fma2(h1, wm1, fma2(h2, wm2, fma2(h3, wm3, 0ull))));
            u64 ad = fma2(h0, wd0, fma2(h1, wd1, fma2(h2, wd2, fma2(h3, wd3, 0ull))));
            u64 ap = fma2(h0, wp0, fma2(h1, wp1, fma2(h2, wp2, fma2(h3, wp3, 0ull))));
            m[s] = unpack_sum(am);
            d[s] = unpack_sum(ad);
            p[s] = unpack_sum(ap);
            C = Cn; G = Gn;
        }

        // ---- reduce-scatter across 8 lanes: 12 SHFL ----
        const bool hi4 = (warpLane & 4) != 0;
        float Am = hi4 ? m[2] : m[0], Ad = hi4 ? d[2] : d[0], Ap = hi4 ? p[2] : p[0];
        float Bm = hi4 ? m[3] : m[1], Bd = hi4 ? d[3] : d[1], Bp = hi4 ? p[3] : p[1];
        Am += __shfl_xor_sync(FULL, hi4 ? m[0] : m[2], 4);
        Ad += __shfl_xor_sync(FULL, hi4 ? d[0] : d[2], 4);
        Ap += __shfl_xor_sync(FULL, hi4 ? p[0] : p[2], 4);
        Bm += __shfl_xor_sync(FULL, hi4 ? m[1] : m[3], 4);
        Bd += __shfl_xor_sync(FULL, hi4 ? d[1] : d[3], 4);
        Bp += __shfl_xor_sync(FULL, hi4 ? p[1] : p[3], 4);
        const bool hi2 = (warpLane & 2) != 0;
        float Rm = hi2 ? Bm : Am, Rd = hi2 ? Bd : Ad, Rp = hi2 ? Bp : Ap;
        Rm += __shfl_xor_sync(FULL, hi2 ? Am : Bm, 2);
        Rd += __shfl_xor_sync(FULL, hi2 ? Ad : Bd, 2);
        Rp += __shfl_xor_sync(FULL, hi2 ? Ap : Bp, 2);
        Rm += __shfl_xor_sync(FULL, Rm, 1);
        Rd += __shfl_xor_sync(FULL, Rd, 1);
        Rp += __shfl_xor_sync(FULL, Rp, 1);

        // ---- epilogue: 16 even lanes, one edge each ----
        const int eo = ebase + eoOff;
        if ((warpLane & 1) == 0 && eo < n_edges) {
            const float mu_ = __fdividef(1.0f, 1.0f + __expf(-(Rm + bm)));
            const float pi  = __fdividef(1.0f, 1.0f + __expf(-(Rp + bp)));
            const float x   = GS * (Rd + bd);
            const float sx  = fmaxf(x, 0.0f) + __logf(1.0f + __expf(-fabsf(x)));
            const float disp = fminf(fmaxf(sx, 1e-4f), 1e4f);
            const float mu  = CS * fminf(fmaxf(__expf(GS * mu_) - 1.0f, 1e-5f), 1e6f);
            out[eo]                       = mu;
            out[(size_t)n_edges + eo]     = disp;
            out[(size_t)2 * n_edges + eo] = pi;
        }

        ia = ib; ib = ic;
        stage ^= 1;
    }
}

extern "C" void kernel_launch(void* const* d_in, const int* in_sizes, int n_in,
                              void* d_out, int out_size) {
    const float* c_feat    = (const float*)d_in[0];
    const float* g_feat    = (const float*)d_in[1];
    const float* cs_factor = (const float*)d_in[2];
    const float* gs_factor = (const float*)d_in[3];
    const int*   edge_u    = (const int*)d_in[4];
    const int*   edge_v    = (const int*)d_in[5];
    const float* W_mean    = (const float*)d_in[6];
    const float* b_mean    = (const float*)d_in[7];
    const float* W_disp    = (const float*)d_in[8];
    const float* b_disp    = (const float*)d_in[9];
    const float* W_pi      = (const float*)d_in[10];
    const float* b_pi      = (const float*)d_in[11];

    const int n_edges = in_sizes[4];
    float* out = (float*)d_out;

    __half* c_h = nullptr;
    __half* g_h = nullptr;
    cudaGetSymbolAddress((void**)&c_h, c_half_tbl);
    cudaGetSymbolAddress((void**)&g_h, g_half_tbl);

    const int c_n8 = in_sizes[0] / 8;
    const int g_n8 = in_sizes[1] / 8;
    cvt_fp16_kernel<<<(c_n8 + g_n8 + 255) / 256, 256>>>(c_feat, c_h, c_n8,
                                                        g_feat, g_h, g_n8);

    static bool attr_set = false;
    if (!attr_set) {
        cudaFuncSetAttribute(zinb_decoder_kernel,
                             cudaFuncAttributeMaxDynamicSharedMemorySize, SMEM_TOTAL);
        attr_set = true;
    }

    const int blocks = 1184;  // 148 SMs * 8
    zinb_decoder_kernel<<<blocks, BLOCK, SMEM_TOTAL>>>(
        c_h, g_h, cs_factor, gs_factor, edge_u, edge_v,
        W_mean, b_mean, W_disp, b_disp, W_pi, b_pi,
        out, n_edges);
}

// round 12
// speedup vs baseline: 1.0658x; 1.0658x over previous
#include <cuda_runtime.h>
#include <cuda_fp16.h>

// ZINB decoder over 3M edges.
// Stage 1: fused fp32 -> fp16 feature-table conversion (row = one 128B line).
// Stage 2: persistent kernel (R8 design + register diet for occupancy):
//   warp = 16 consecutive edges/iter, 4 sets x 4 groups (8 lanes/edge),
//   f32x2 packed-FMA dots, reduce-scatter (12 SHFL), 16-lane fast-math
//   epilogue, coalesced stores, 1-tile-ahead index prefetch.
//   DIET: (u,v) packed into one 32-bit reg per set (u<2^16, v<2^16),
//   32-bit byte offsets, __launch_bounds__(256,4) -> 4 blocks/SM (32 warps).

#define BLOCK 256
#define N_CELLS_MAX 50000
#define N_GENES_MAX 20000

__device__ __align__(16) static __half c_half_tbl[N_CELLS_MAX * 64];
__device__ __align__(16) static __half g_half_tbl[N_GENES_MAX * 64];

typedef unsigned long long u64;

__device__ __forceinline__ u64 pack2(float x, float y) {
    u64 r; asm("mov.b64 %0, {%1,%2};" : "=l"(r) : "f"(x), "f"(y)); return r;
}
__device__ __forceinline__ u64 fma2(u64 a, u64 b, u64 c) {
    u64 d; asm("fma.rn.f32x2 %0, %1, %2, %3;" : "=l"(d) : "l"(a), "l"(b), "l"(c)); return d;
}
__device__ __forceinline__ float unpack_sum(u64 v) {
    float lo, hi; asm("mov.b64 {%0,%1}, %2;" : "=f"(lo), "=f"(hi) : "l"(v));
    return lo + hi;
}
__device__ __forceinline__ unsigned int h2_as_u32(__half2 h) {
    return *reinterpret_cast<unsigned int*>(&h);
}

// Fused fp32 -> fp16 conversion for both tables (8 floats per thread).
__global__ __launch_bounds__(256)
void cvt_fp16_kernel(const float* __restrict__ srcA, __half* __restrict__ dstA, int nA8,
                     const float* __restrict__ srcB, __half* __restrict__ dstB, int nB8) {
    int i = blockIdx.x * blockDim.x + threadIdx.x;
    const float* src; __half* dst; int j;
    if (i < nA8) { src = srcA; dst = dstA; j = i; }
    else if (i < nA8 + nB8) { src = srcB; dst = dstB; j = i - nA8; }
    else return;
    const float4* s = reinterpret_cast<const float4*>(src) + 2 * (size_t)j;
    const float4 a = s[0], b = s[1];
    uint4 o;
    o.x = h2_as_u32(__floats2half2_rn(a.x, a.y));
    o.y = h2_as_u32(__floats2half2_rn(a.z, a.w));
    o.z = h2_as_u32(__floats2half2_rn(b.x, b.y));
    o.w = h2_as_u32(__floats2half2_rn(b.z, b.w));
    reinterpret_cast<uint4*>(dst)[j] = o;
}

// packed index tile: p = u | (v << 16); 4 regs instead of 8
struct IdxTile { unsigned p0, p1, p2, p3; };

__device__ __forceinline__ IdxTile load_idx(const int* __restrict__ eu,
                                            const int* __restrict__ ev,
                                            int ebase, int grp, int n_edges) {
    const int e0 = ebase + grp;
    const int ec0 = (e0      < n_edges) ? e0      : 0;
    const int ec1 = (e0 + 4  < n_edges) ? e0 + 4  : 0;
    const int ec2 = (e0 + 8  < n_edges) ? e0 + 8  : 0;
    const int ec3 = (e0 + 12 < n_edges) ? e0 + 12 : 0;
    IdxTile t;
    t.p0 = (unsigned)eu[ec0] | ((unsigned)ev[ec0] << 16);
    t.p1 = (unsigned)eu[ec1] | ((unsigned)ev[ec1] << 16);
    t.p2 = (unsigned)eu[ec2] | ((unsigned)ev[ec2] << 16);
    t.p3 = (unsigned)eu[ec3] | ((unsigned)ev[ec3] << 16);
    return t;
}

__device__ __forceinline__ uint4 ld_row(const char* __restrict__ base, unsigned off) {
    return *reinterpret_cast<const uint4*>(base + off);
}

__global__ __launch_bounds__(BLOCK, 4)
void zinb_decoder_kernel(const __half* __restrict__ c_feat,
                         const __half* __restrict__ g_feat,
                         const float* __restrict__ cs_factor,
                         const float* __restrict__ gs_factor,
                         const int*   __restrict__ edge_u,
                         const int*   __restrict__ edge_v,
                         const float* __restrict__ W_mean,
                         const float* __restrict__ b_mean,
                         const float* __restrict__ W_disp,
                         const float* __restrict__ b_disp,
                         const float* __restrict__ W_pi,
                         const float* __restrict__ b_pi,
                         float* __restrict__ out,
                         int n_edges)
{
    const unsigned FULL = 0xffffffffu;
    const int warpLane = threadIdx.x & 31;
    const int grp      = warpLane >> 3;
    const int lane8    = warpLane & 7;
    const int sl       = ((warpLane & 4) >> 1) | ((warpLane & 2) >> 1);
    const int eoOff    = 4 * sl + grp;
    const unsigned l16 = (unsigned)(lane8 * 16);

    // ---- weights packed as f32x2, biases ----
    const float4* wmv = reinterpret_cast<const float4*>(W_mean) + lane8 * 2;
    const float4* wdv = reinterpret_cast<const float4*>(W_disp) + lane8 * 2;
    const float4* wpv = reinterpret_cast<const float4*>(W_pi)   + lane8 * 2;
    const float4 a0 = __ldg(wmv), a1 = __ldg(wmv + 1);
    const float4 d0 = __ldg(wdv), d1 = __ldg(wdv + 1);
    const float4 p0 = __ldg(wpv), p1 = __ldg(wpv + 1);
    const u64 wm0 = pack2(a0.x, a0.y), wm1 = pack2(a0.z, a0.w),
              wm2 = pack2(a1.x, a1.y), wm3 = pack2(a1.z, a1.w);
    const u64 wd0 = pack2(d0.x, d0.y), wd1 = pack2(d0.z, d0.w),
              wd2 = pack2(d1.x, d1.y), wd3 = pack2(d1.z, d1.w);
    const u64 wp0 = pack2(p0.x, p0.y), wp1 = pack2(p0.z, p0.w),
              wp2 = pack2(p1.x, p1.y), wp3 = pack2(p1.z, p1.w);
    const float bm = __ldg(b_mean), bd = __ldg(b_disp), bp = __ldg(b_pi);

    const int warpId  = (blockIdx.x * BLOCK + threadIdx.x) >> 5;
    const int nWarps  = gridDim.x * (BLOCK >> 5);
    const int tileStr = nWarps * 16;

    const char* cb = reinterpret_cast<const char*>(c_feat);
    const char* gb = reinterpret_cast<const char*>(g_feat);

    const int e0 = warpId * 16;
    if (e0 >= n_edges) return;

    // ---- prime index pipeline ----
    IdxTile ia = load_idx(edge_u, edge_v, e0,           grp, n_edges);
    IdxTile ib = load_idx(edge_u, edge_v, e0 + tileStr, grp, n_edges);

    for (int ebase = e0; ebase < n_edges; ebase += tileStr) {
        // ---- feature gathers (32-bit byte offsets from packed idx) ----
        const uint4 C0 = ld_row(cb, ((ia.p0 & 0xFFFFu) << 7) + l16);
        const uint4 G0 = ld_row(gb, ((ia.p0 >> 16)     << 7) + l16);
        const uint4 C1 = ld_row(cb, ((ia.p1 & 0xFFFFu) << 7) + l16);
        const uint4 G1 = ld_row(gb, ((ia.p1 >> 16)     << 7) + l16);
        const uint4 C2 = ld_row(cb, ((ia.p2 & 0xFFFFu) << 7) + l16);
        const uint4 G2 = ld_row(gb, ((ia.p2 >> 16)     << 7) + l16);
        const uint4 C3 = ld_row(cb, ((ia.p3 & 0xFFFFu) << 7) + l16);
        const uint4 G3 = ld_row(gb, ((ia.p3 >> 16)     << 7) + l16);

        // ---- cs/gs scattered gathers (small cache-resident tables) ----
        const unsigned pSel = sl < 2 ? (sl == 0 ? ia.p0 : ia.p1)
                                     : (sl == 2 ? ia.p2 : ia.p3);
        const float GS = gs_factor[pSel >> 16];
        const float CS = cs_factor[pSel & 0xFFFFu];

        // ---- prefetch indices for tile t+2 (overlaps compute) ----
        const IdxTile ic = load_idx(edge_u, edge_v, ebase + 2 * tileStr, grp, n_edges);

        float m[4], d[4], p[4];
        #pragma unroll
        for (int s = 0; s < 4; s++) {
            const uint4& C = s == 0 ? C0 : s == 1 ? C1 : s == 2 ? C2 : C3;
            const uint4& G = s == 0 ? G0 : s == 1 ? G1 : s == 2 ? G2 : G3;
            const __half2* ch = reinterpret_cast<const __half2*>(&C);
            const __half2* gh = reinterpret_cast<const __half2*>(&G);
            const float2 q0 = __half22float2(__hmul2(ch[0], gh[0]));
            const float2 q1 = __half22float2(__hmul2(ch[1], gh[1]));
            const float2 q2 = __half22float2(__hmul2(ch[2], gh[2]));
            const float2 q3 = __half22float2(__hmul2(ch[3], gh[3]));
            const u64 h0 = pack2(q0.x, q0.y), h1 = pack2(q1.x, q1.y);
            const u64 h2 = pack2(q2.x, q2.y), h3 = pack2(q3.x, q3.y);
            u64 am = fma2(h0, wm0, fma2(h1, wm1, fma2(h2, wm2, fma2(h3, wm3, 0ull))));
            u64 ad = fma2(h0, wd0, fma2(h1, wd1, fma2(h2, wd2, fma2(h3, wd3, 0ull))));
            u64 ap = fma2(h0, wp0, fma2(h1, wp1, fma2(h2, wp2, fma2(h3, wp3, 0ull))));
            m[s] = unpack_sum(am);
            d[s] = unpack_sum(ad);
            p[s] = unpack_sum(ap);
        }

        // ---- reduce-scatter across 8 lanes: 12 SHFL ----
        const bool hi4 = (warpLane & 4) != 0;
        float Am = hi4 ? m[2] : m[0], Ad = hi4 ? d[2] : d[0], Ap = hi4 ? p[2] : p[0];
        float Bm = hi4 ? m[3] : m[1], Bd = hi4 ? d[3] : d[1], Bp = hi4 ? p[3] : p[1];
        Am += __shfl_xor_sync(FULL, hi4 ? m[0] : m[2], 4);
        Ad += __shfl_xor_sync(FULL, hi4 ? d[0] : d[2], 4);
        Ap += __shfl_xor_sync(FULL, hi4 ? p[0] : p[2], 4);
        Bm += __shfl_xor_sync(FULL, hi4 ? m[1] : m[3], 4);
        Bd += __shfl_xor_sync(FULL, hi4 ? d[1] : d[3], 4);
        Bp += __shfl_xor_sync(FULL, hi4 ? p[1] : p[3], 4);
        const bool hi2 = (warpLane & 2) != 0;
        float Rm = hi2 ? Bm : Am, Rd = hi2 ? Bd : Ad, Rp = hi2 ? Bp : Ap;
        Rm += __shfl_xor_sync(FULL, hi2 ? Am : Bm, 2);
        Rd += __shfl_xor_sync(FULL, hi2 ? Ad : Bd, 2);
        Rp += __shfl_xor_sync(FULL, hi2 ? Ap : Bp, 2);
        Rm += __shfl_xor_sync(FULL, Rm, 1);
        Rd += __shfl_xor_sync(FULL, Rd, 1);
        Rp += __shfl_xor_sync(FULL, Rp, 1);

        // ---- epilogue: 16 even lanes, one edge each ----
        const int eo = ebase + eoOff;
        if ((warpLane & 1) == 0 && eo < n_edges) {
            const float mu_ = __fdividef(1.0f, 1.0f + __expf(-(Rm + bm)));
            const float pi  = __fdividef(1.0f, 1.0f + __expf(-(Rp + bp)));
            const float x   = GS * (Rd + bd);
            const float sx  = fmaxf(x, 0.0f) + __logf(1.0f + __expf(-fabsf(x)));
            const float disp = fminf(fmaxf(sx, 1e-4f), 1e4f);
            const float mu  = CS * fminf(fmaxf(__expf(GS * mu_) - 1.0f, 1e-5f), 1e6f);
            out[eo]                       = mu;
            out[(size_t)n_edges + eo]     = disp;
            out[(size_t)2 * n_edges + eo] = pi;
        }

        ia = ib; ib = ic;
    }
}

extern "C" void kernel_launch(void* const* d_in, const int* in_sizes, int n_in,
                              void* d_out, int out_size) {
    const float* c_feat    = (const float*)d_in[0];
    const float* g_feat    = (const float*)d_in[1];
    const float* cs_factor = (const float*)d_in[2];
    const float* gs_factor = (const float*)d_in[3];
    const int*   edge_u    = (const int*)d_in[4];
    const int*   edge_v    = (const int*)d_in[5];
    const float* W_mean    = (const float*)d_in[6];
    const float* b_mean    = (const float*)d_in[7];
    const float* W_disp    = (const float*)d_in[8];
    const float* b_disp    = (const float*)d_in[9];
    const float* W_pi      = (const float*)d_in[10];
    const float* b_pi      = (const float*)d_in[11];

    const int n_edges = in_sizes[4];
    float* out = (float*)d_out;

    __half* c_h = nullptr;
    __half* g_h = nullptr;
    cudaGetSymbolAddress((void**)&c_h, c_half_tbl);
    cudaGetSymbolAddress((void**)&g_h, g_half_tbl);

    const int c_n8 = in_sizes[0] / 8;
    const int g_n8 = in_sizes[1] / 8;
    cvt_fp16_kernel<<<(c_n8 + g_n8 + 255) / 256, 256>>>(c_feat, c_h, c_n8,
                                                        g_feat, g_h, g_n8);

    const int blocks = 1184;  // 148 SMs * 8
    zinb_decoder_kernel<<<blocks, BLOCK>>>(
        c_h, g_h, cs_factor, gs_factor, edge_u, edge_v,
        W_mean, b_mean, W_disp, b_disp, W_pi, b_pi,
        out, n_edges);
}